// round 12
// baseline (speedup 1.0000x reference)
#include <cuda_runtime.h>
#include <cstdint>

typedef unsigned long long ull;

#define Bn   8
#define N1   8192
#define N2   2048
#define KNN  16
#define HID  64
#define OUTC 128
#define NQ   (Bn * N1)

// ---------------- scratch (static device globals; no allocation) ----------------
__device__ int   g_idx[NQ * KNN];          // 4 MB
__device__ float g_G2 [Bn * N2 * HID];     // 4 MB   G2 = feat2 @ W1_0[:64] + b1_0
__device__ float g_P  [NQ * HID];          // 16 MB  pooled layer-2 output

// ---------------- packed f32x2 helpers ----------------
__device__ __forceinline__ void ffma2(ull &d, ull a, ull b) {
    asm("fma.rn.f32x2 %0, %1, %2, %0;" : "+l"(d) : "l"(a), "l"(b));
}
__device__ __forceinline__ ull pack2(float x, float y) {
    ull r; asm("mov.b64 %0, {%1, %2};" : "=l"(r) : "f"(x), "f"(y)); return r;
}
__device__ __forceinline__ void unpack2(ull v, float &x, float &y) {
    asm("mov.b64 {%0, %1}, %2;" : "=f"(x), "=f"(y) : "l"(v));
}
__device__ __forceinline__ float inff() { return __int_as_float(0x7f800000); }

// ---------------- P1: G2 = feat2 @ W1_0[0:64,:] + b1_0 (2 points/thread) ----------------
__global__ void __launch_bounds__(256) g2_kernel(const float* __restrict__ feat2,
                                                 const float* __restrict__ W1_0,
                                                 const float* __restrict__ b1_0) {
    __shared__ float sf[8][64];
    int sub = threadIdx.x >> 6;
    int ch  = threadIdx.x & 63;
    int ptb = blockIdx.x * 8;
    sf[sub][ch]     = feat2[(ptb + sub) * 64 + ch];
    sf[sub + 4][ch] = feat2[(ptb + sub + 4) * 64 + ch];
    __syncthreads();
    const float* r0 = sf[sub];
    const float* r1 = sf[sub + 4];
    float acc0 = b1_0[ch], acc1 = acc0;
#pragma unroll 16
    for (int c = 0; c < 64; ++c) {
        float wv = W1_0[c * 64 + ch];
        acc0 = fmaf(r0[c], wv, acc0);
        acc1 = fmaf(r1[c], wv, acc1);
    }
    g_G2[(ptb + sub) * 64 + ch]     = acc0;
    g_G2[(ptb + sub + 4) * 64 + ch] = acc1;
}

// ---------------- kNN: one query per thread, two-phase select ----------------
__device__ __forceinline__ float distf(float4 p, float x, float y, float z) {
    float t = p.x * x;
    t = fmaf(p.y, y, t);
    t = fmaf(p.z, z, t);
    return fmaf(-2.0f, t, p.w);
}

__global__ void __launch_bounds__(128) knn_kernel(const float* __restrict__ xyz1,
                                                  const float* __restrict__ xyz2) {
    __shared__ float4 s2[N2];                 // 32 KB: (x,y,z,|p|^2)
    int b = blockIdx.y;
    const float* x2 = xyz2 + (size_t)b * N2 * 3;
    for (int i = threadIdx.x; i < N2; i += 128) {
        float px = x2[i * 3 + 0], py = x2[i * 3 + 1], pz = x2[i * 3 + 2];
        s2[i] = make_float4(px, py, pz, fmaf(px, px, fmaf(py, py, pz * pz)));
    }
    __syncthreads();

    int n = blockIdx.x * 128 + threadIdx.x;   // query within batch
    int q = b * N1 + n;
    float x1x = xyz1[q * 3 + 0], x1y = xyz1[q * 3 + 1], x1z = xyz1[q * 3 + 2];

    // phase 1: exact 16th-smallest (shifted) distance via branch-free sorted chain
    float best[KNN];
#pragma unroll
    for (int i = 0; i < KNN; ++i) best[i] = inff();

    for (int c = 0; c < N2; ++c) {
        float4 p = s2[c];
        float d = distf(p, x1x, x1y, x1z);
        bool act = d < best[KNN - 1];
        if (__ballot_sync(0xffffffffu, act)) {
            float v = act ? d : inff();       // INF insert = no-op, keeps warp uniform
#pragma unroll
            for (int i = 0; i < KNN; ++i) {
                float t = fminf(v, best[i]);
                v = fmaxf(v, best[i]);
                best[i] = t;
            }
        }
    }
    float tau = best[KNN - 1];

    // phase 2: collect indices with d <= tau (identical arithmetic), cap at 16
    int cnt = 0, lastc = 0;
    int* myout = g_idx + (size_t)q * KNN;
    for (int c = 0; c < N2; ++c) {
        float4 p = s2[c];
        float d = distf(p, x1x, x1y, x1z);
        if (d <= tau && cnt < KNN) {
            myout[cnt++] = c;
            lastc = c;
        }
    }
    for (; cnt < KNN; ++cnt) myout[cnt] = lastc;   // safety fill (ties/ulp)
}

// ---------------- mlp_core: layer1 + layer2 + maxpool -> g_P ----------------
#define CWARPS   8
#define CTHREADS 256
#define HS       20                        // 16 k-slots + 4 pad (16B-aligned rows)
#define SW11_F   4096                      // 64*64 W1_1 (not duplicated)
#define SHW_F    (64 * HS)                 // per-warp H1 buffer (1280 floats)
#define CSMEM_F  (SW11_F + CWARPS * SHW_F + CWARPS * 16)
#define CSMEM_B  (CSMEM_F * 4)             // ~57 KB -> 3 blocks/SM

__global__ void __launch_bounds__(CTHREADS, 3)
mlp_core(const float* __restrict__ xyz1, const float* __restrict__ xyz2,
         const float* __restrict__ W1_0, const float* __restrict__ W1_1,
         const float* __restrict__ b1_1) {
    extern __shared__ float sm[];
    float* sW11 = sm;
    float* sH   = sm + SW11_F;
    int*   sIdx = (int*)(sm + SW11_F + CWARPS * SHW_F);

    int tid = threadIdx.x, w = tid >> 5, lane = tid & 31;

    for (int i = tid; i < SW11_F; i += CTHREADS) sW11[i] = W1_1[i];

    // per-lane constants: xyz rows of W1_0 for channels (lane, lane+32); layer-2 bias
    float wxa = W1_0[64 * 64 + lane],      wxb = W1_0[64 * 64 + lane + 32];
    float wya = W1_0[65 * 64 + lane],      wyb = W1_0[65 * 64 + lane + 32];
    float wza = W1_0[66 * 64 + lane],      wzb = W1_0[66 * 64 + lane + 32];
    float bb0 = b1_1[2 * lane], bb1 = b1_1[2 * lane + 1];
    __syncthreads();

    float* myH   = sH + w * SHW_F;
    int*   myIdx = sIdx + w * 16;
    const int nwarps = gridDim.x * CWARPS;

    for (int q = blockIdx.x * CWARPS + w; q < NQ; q += nwarps) {
        int b = q >> 13;
        if (lane < 16) myIdx[lane] = g_idx[(size_t)q * KNN + lane];
        float x1x = xyz1[q * 3 + 0], x1y = xyz1[q * 3 + 1], x1z = xyz1[q * 3 + 2];
        __syncwarp();

        // ---- layer 1: lane owns channels (lane, lane+32) ----
#pragma unroll
        for (int k = 0; k < KNN; ++k) {
            int ik = myIdx[k];
            const float* gr = g_G2 + ((size_t)(b << 11) + ik) * 64;
            float g0 = gr[lane], g1 = gr[lane + 32];
            const float* p2 = xyz2 + ((size_t)(b << 11) + ik) * 3;
            float dx = p2[0] - x1x, dy = p2[1] - x1y, dz = p2[2] - x1z;
            float h0 = fmaf(dz, wza, fmaf(dy, wya, fmaf(dx, wxa, g0)));
            float h1 = fmaf(dz, wzb, fmaf(dy, wyb, fmaf(dx, wxb, g1)));
            myH[lane * HS + k]        = fmaxf(h0, 0.f);
            myH[(lane + 32) * HS + k] = fmaxf(h1, 0.f);
        }
        __syncwarp();

        // ---- layer 2: FFMA2, 16B broadcast H reads, pack weights on the fly ----
        ull acc0[8], acc1[8];
#pragma unroll
        for (int kk = 0; kk < 8; ++kk) { acc0[kk] = 0ull; acc1[kk] = 0ull; }
#pragma unroll 4
        for (int c = 0; c < 64; ++c) {
            float2 wv = *(const float2*)&sW11[c * 64 + 2 * lane];
            ull w0 = pack2(wv.x, wv.x);
            ull w1 = pack2(wv.y, wv.y);
            const float* hr = myH + c * HS;
#pragma unroll
            for (int kk = 0; kk < 4; ++kk) {
                ulonglong2 hv = *(const ulonglong2*)(hr + 4 * kk);  // h[4kk..4kk+3]
                ffma2(acc0[2 * kk],     hv.x, w0);
                ffma2(acc0[2 * kk + 1], hv.y, w0);
                ffma2(acc1[2 * kk],     hv.x, w1);
                ffma2(acc1[2 * kk + 1], hv.y, w1);
            }
        }

        // ---- maxpool over k, bias, relu -> g_P ----
        float m0 = -inff(), m1 = -inff();
#pragma unroll
        for (int kk = 0; kk < 8; ++kk) {
            float a, bh;
            unpack2(acc0[kk], a, bh); m0 = fmaxf(m0, fmaxf(a, bh));
            unpack2(acc1[kk], a, bh); m1 = fmaxf(m1, fmaxf(a, bh));
        }
        float p0 = fmaxf(m0 + bb0, 0.f);
        float p1 = fmaxf(m1 + bb1, 0.f);
        *(float2*)&g_P[(size_t)q * 64 + 2 * lane] = make_float2(p0, p1);
        __syncwarp();
    }
}

// ---------------- final GEMM: out = relu([g_P | feat1] @ W2_0 + b2_0) ----------------
// block: 64 queries x 128 j; thread: 2 queries x 16 j; 24 warps/SM
#define GTHREADS 256
#define AS_S 36                            // duplicated A row: 16c*2 + 4 pad (16B aligned)

__global__ void __launch_bounds__(GTHREADS, 3)
gemm_final(const float* __restrict__ feat1, const float* __restrict__ W2_0,
           const float* __restrict__ b2_0, float* __restrict__ out) {
    __shared__ float As[64 * AS_S];        // 9 KB   A tile [64 q][16 c] duplicated (v,v)
    __shared__ float Bs[16 * 128];         // 8 KB   B tile [16 c][128 j]

    int tid  = threadIdx.x;
    int qg   = tid >> 3;                   // 0..31  -> rows qg, qg+32
    int jblk = tid & 7;                    // 0..7   -> j = jblk*16 .. +16
    int qb   = blockIdx.x * 64;

    ull acc[2][8];
#pragma unroll
    for (int m = 0; m < 2; ++m)
#pragma unroll
        for (int j = 0; j < 8; ++j) acc[m][j] = 0ull;

    // staging roles
    int ar = tid >> 2, ap = tid & 3;       // A: row ar (0..63), c-quad ap
    int br = tid >> 4, bc = (tid & 15) * 8;// B: row br (0..15), 8 cols at bc

    for (int ch = 0; ch < 8; ++ch) {       // 16 c per chunk
        __syncthreads();
        // ---- stage B: W2_0 rows [ch*16, +16) ----
        {
            const float* src = W2_0 + (ch * 16 + br) * 128 + bc;
            float4 v0 = *(const float4*)(src);
            float4 v1 = *(const float4*)(src + 4);
            *(float4*)&Bs[br * 128 + bc]     = v0;
            *(float4*)&Bs[br * 128 + bc + 4] = v1;
        }
        // ---- stage A duplicated: [g_P | feat1] cols [ch*16,+16) for 64 queries ----
        {
            const float* src = (ch < 4)
                ? (g_P   + (size_t)(qb + ar) * 64 + ch * 16)
                : (feat1 + (size_t)(qb + ar) * 64 + (ch - 4) * 16);
            float4 v = *(const float4*)(src + ap * 4);
            *(float4*)&As[ar * AS_S + 8 * ap]     = make_float4(v.x, v.x, v.y, v.y);
            *(float4*)&As[ar * AS_S + 8 * ap + 4] = make_float4(v.z, v.z, v.w, v.w);
        }
        __syncthreads();

#pragma unroll
        for (int cc = 0; cc < 16; ++cc) {
            ull ad0 = *(const ull*)&As[qg * AS_S + 2 * cc];          // (a,a)
            ull ad1 = *(const ull*)&As[(qg + 32) * AS_S + 2 * cc];
            const float* brow = Bs + cc * 128 + jblk * 16;
            ulonglong2 w01 = *(const ulonglong2*)(brow);
            ulonglong2 w23 = *(const ulonglong2*)(brow + 4);
            ulonglong2 w45 = *(const ulonglong2*)(brow + 8);
            ulonglong2 w67 = *(const ulonglong2*)(brow + 12);
            ffma2(acc[0][0], ad0, w01.x);  ffma2(acc[1][0], ad1, w01.x);
            ffma2(acc[0][1], ad0, w01.y);  ffma2(acc[1][1], ad1, w01.y);
            ffma2(acc[0][2], ad0, w23.x);  ffma2(acc[1][2], ad1, w23.x);
            ffma2(acc[0][3], ad0, w23.y);  ffma2(acc[1][3], ad1, w23.y);
            ffma2(acc[0][4], ad0, w45.x);  ffma2(acc[1][4], ad1, w45.x);
            ffma2(acc[0][5], ad0, w45.y);  ffma2(acc[1][5], ad1, w45.y);
            ffma2(acc[0][6], ad0, w67.x);  ffma2(acc[1][6], ad1, w67.x);
            ffma2(acc[0][7], ad0, w67.y);  ffma2(acc[1][7], ad1, w67.y);
        }
    }

    // ---- bias + relu + store ----
    float bias[16];
#pragma unroll
    for (int j = 0; j < 4; ++j)
        *(float4*)&bias[4 * j] = *(const float4*)&b2_0[jblk * 16 + 4 * j];

#pragma unroll
    for (int m = 0; m < 2; ++m) {
        int qq = qb + qg + 32 * m;
        float r[16];
#pragma unroll
        for (int j = 0; j < 8; ++j) {
            float a, bvl;
            unpack2(acc[m][j], a, bvl);
            r[2 * j]     = fmaxf(a   + bias[2 * j],     0.f);
            r[2 * j + 1] = fmaxf(bvl + bias[2 * j + 1], 0.f);
        }
#pragma unroll
        for (int j = 0; j < 4; ++j)
            *(float4*)&out[(size_t)qq * OUTC + jblk * 16 + 4 * j] =
                make_float4(r[4 * j], r[4 * j + 1], r[4 * j + 2], r[4 * j + 3]);
    }
}

// ---------------- launch ----------------
extern "C" void kernel_launch(void* const* d_in, const int* in_sizes, int n_in,
                              void* d_out, int out_size) {
    const float* xyz1  = (const float*)d_in[0];
    const float* feat1 = (const float*)d_in[1];
    const float* xyz2  = (const float*)d_in[2];
    const float* feat2 = (const float*)d_in[3];
    const float* W1_0  = (const float*)d_in[4];
    const float* b1_0  = (const float*)d_in[5];
    const float* W1_1  = (const float*)d_in[6];
    const float* b1_1  = (const float*)d_in[7];
    const float* W2_0  = (const float*)d_in[8];
    const float* b2_0  = (const float*)d_in[9];
    float* out = (float*)d_out;

    cudaFuncSetAttribute(mlp_core, cudaFuncAttributeMaxDynamicSharedMemorySize,
                         CSMEM_B);

    g2_kernel<<<(Bn * N2) / 8, 256>>>(feat2, W1_0, b1_0);
    knn_kernel<<<dim3(N1 / 128, Bn), 128>>>(xyz1, xyz2);
    mlp_core<<<444, CTHREADS, CSMEM_B>>>(xyz1, xyz2, W1_0, W1_1, b1_1);
    gemm_final<<<NQ / 64, GTHREADS>>>(feat1, W2_0, b2_0, out);
}

// round 13
// speedup vs baseline: 1.0007x; 1.0007x over previous
#include <cuda_runtime.h>
#include <cstdint>

typedef unsigned long long ull;

#define Bn   8
#define N1   8192
#define N2   2048
#define KNN  16
#define HID  64
#define OUTC 128
#define NQ   (Bn * N1)

// ---------------- scratch (static device globals; no allocation) ----------------
__device__ int   g_idx[NQ * KNN];          // 4 MB
__device__ float g_G2 [Bn * N2 * HID];     // 4 MB   G2 = feat2 @ W1_0[:64] + b1_0
__device__ float g_P  [NQ * HID];          // 16 MB  pooled layer-2 output

// ---------------- packed f32x2 helpers ----------------
__device__ __forceinline__ void ffma2(ull &d, ull a, ull b) {
    asm("fma.rn.f32x2 %0, %1, %2, %0;" : "+l"(d) : "l"(a), "l"(b));
}
__device__ __forceinline__ ull pack2(float x, float y) {
    ull r; asm("mov.b64 %0, {%1, %2};" : "=l"(r) : "f"(x), "f"(y)); return r;
}
__device__ __forceinline__ void unpack2(ull v, float &x, float &y) {
    asm("mov.b64 {%0, %1}, %2;" : "=f"(x), "=f"(y) : "l"(v));
}
__device__ __forceinline__ float inff() { return __int_as_float(0x7f800000); }

// ---------------- P1: G2 = feat2 @ W1_0[0:64,:] + b1_0 (2 points/thread) ----------------
__global__ void __launch_bounds__(256) g2_kernel(const float* __restrict__ feat2,
                                                 const float* __restrict__ W1_0,
                                                 const float* __restrict__ b1_0) {
    __shared__ float sf[8][64];
    int sub = threadIdx.x >> 6;
    int ch  = threadIdx.x & 63;
    int ptb = blockIdx.x * 8;
    sf[sub][ch]     = feat2[(ptb + sub) * 64 + ch];
    sf[sub + 4][ch] = feat2[(ptb + sub + 4) * 64 + ch];
    __syncthreads();
    const float* r0 = sf[sub];
    const float* r1 = sf[sub + 4];
    float acc0 = b1_0[ch], acc1 = acc0;
#pragma unroll 16
    for (int c = 0; c < 64; ++c) {
        float wv = W1_0[c * 64 + ch];
        acc0 = fmaf(r0[c], wv, acc0);
        acc1 = fmaf(r1[c], wv, acc1);
    }
    g_G2[(ptb + sub) * 64 + ch]     = acc0;
    g_G2[(ptb + sub + 4) * 64 + ch] = acc1;
}

// ---------------- kNN: one query per thread, two-phase select ----------------
__device__ __forceinline__ float distf(float4 p, float x, float y, float z) {
    float t = p.x * x;
    t = fmaf(p.y, y, t);
    t = fmaf(p.z, z, t);
    return fmaf(-2.0f, t, p.w);
}

__global__ void __launch_bounds__(128) knn_kernel(const float* __restrict__ xyz1,
                                                  const float* __restrict__ xyz2) {
    __shared__ float4 s2[N2];                 // 32 KB: (x,y,z,|p|^2)
    int b = blockIdx.y;
    const float* x2 = xyz2 + (size_t)b * N2 * 3;
    for (int i = threadIdx.x; i < N2; i += 128) {
        float px = x2[i * 3 + 0], py = x2[i * 3 + 1], pz = x2[i * 3 + 2];
        s2[i] = make_float4(px, py, pz, fmaf(px, px, fmaf(py, py, pz * pz)));
    }
    __syncthreads();

    int n = blockIdx.x * 128 + threadIdx.x;   // query within batch
    int q = b * N1 + n;
    float x1x = xyz1[q * 3 + 0], x1y = xyz1[q * 3 + 1], x1z = xyz1[q * 3 + 2];

    // phase 1: exact 16th-smallest (shifted) distance via branch-free sorted chain
    float best[KNN];
#pragma unroll
    for (int i = 0; i < KNN; ++i) best[i] = inff();

    for (int c = 0; c < N2; ++c) {
        float4 p = s2[c];
        float d = distf(p, x1x, x1y, x1z);
        bool act = d < best[KNN - 1];
        if (__ballot_sync(0xffffffffu, act)) {
            float v = act ? d : inff();       // INF insert = no-op, keeps warp uniform
#pragma unroll
            for (int i = 0; i < KNN; ++i) {
                float t = fminf(v, best[i]);
                v = fmaxf(v, best[i]);
                best[i] = t;
            }
        }
    }
    float tau = best[KNN - 1];

    // phase 2: collect indices with d <= tau (identical arithmetic), cap at 16
    int cnt = 0, lastc = 0;
    int* myout = g_idx + (size_t)q * KNN;
    for (int c = 0; c < N2; ++c) {
        float4 p = s2[c];
        float d = distf(p, x1x, x1y, x1z);
        if (d <= tau && cnt < KNN) {
            myout[cnt++] = c;
            lastc = c;
        }
    }
    for (; cnt < KNN; ++cnt) myout[cnt] = lastc;   // safety fill (ties/ulp)
}

// ---------------- mlp_core: layer1 + layer2 + maxpool -> g_P ----------------
#define CWARPS   8
#define CTHREADS 256
#define HS       20                        // 16 k-slots + 4 pad (16B-aligned rows)
#define SW11_F   4096                      // 64*64 W1_1 (not duplicated)
#define SHW_F    (64 * HS)                 // per-warp H1 buffer (1280 floats)
#define CSMEM_F  (SW11_F + CWARPS * SHW_F + CWARPS * 16)
#define CSMEM_B  (CSMEM_F * 4)             // ~57 KB -> 3 blocks/SM

__global__ void __launch_bounds__(CTHREADS, 3)
mlp_core(const float* __restrict__ xyz1, const float* __restrict__ xyz2,
         const float* __restrict__ W1_0, const float* __restrict__ W1_1,
         const float* __restrict__ b1_1) {
    extern __shared__ float sm[];
    float* sW11 = sm;
    float* sH   = sm + SW11_F;
    int*   sIdx = (int*)(sm + SW11_F + CWARPS * SHW_F);

    int tid = threadIdx.x, w = tid >> 5, lane = tid & 31;

    for (int i = tid; i < SW11_F; i += CTHREADS) sW11[i] = W1_1[i];

    // per-lane constants: xyz rows of W1_0 for channels (lane, lane+32); layer-2 bias
    float wxa = W1_0[64 * 64 + lane],      wxb = W1_0[64 * 64 + lane + 32];
    float wya = W1_0[65 * 64 + lane],      wyb = W1_0[65 * 64 + lane + 32];
    float wza = W1_0[66 * 64 + lane],      wzb = W1_0[66 * 64 + lane + 32];
    float bb0 = b1_1[2 * lane], bb1 = b1_1[2 * lane + 1];
    __syncthreads();

    float* myH   = sH + w * SHW_F;
    int*   myIdx = sIdx + w * 16;
    const int nwarps = gridDim.x * CWARPS;

    for (int q = blockIdx.x * CWARPS + w; q < NQ; q += nwarps) {
        int b = q >> 13;
        if (lane < 16) myIdx[lane] = g_idx[(size_t)q * KNN + lane];
        float x1x = xyz1[q * 3 + 0], x1y = xyz1[q * 3 + 1], x1z = xyz1[q * 3 + 2];
        __syncwarp();

        // ---- layer 1: lane owns channels (lane, lane+32) ----
#pragma unroll
        for (int k = 0; k < KNN; ++k) {
            int ik = myIdx[k];
            const float* gr = g_G2 + ((size_t)(b << 11) + ik) * 64;
            float g0 = gr[lane], g1 = gr[lane + 32];
            const float* p2 = xyz2 + ((size_t)(b << 11) + ik) * 3;
            float dx = p2[0] - x1x, dy = p2[1] - x1y, dz = p2[2] - x1z;
            float h0 = fmaf(dz, wza, fmaf(dy, wya, fmaf(dx, wxa, g0)));
            float h1 = fmaf(dz, wzb, fmaf(dy, wyb, fmaf(dx, wxb, g1)));
            myH[lane * HS + k]        = fmaxf(h0, 0.f);
            myH[(lane + 32) * HS + k] = fmaxf(h1, 0.f);
        }
        __syncwarp();

        // ---- layer 2: FFMA2, 16B broadcast H reads, pack weights on the fly ----
        ull acc0[8], acc1[8];
#pragma unroll
        for (int kk = 0; kk < 8; ++kk) { acc0[kk] = 0ull; acc1[kk] = 0ull; }
#pragma unroll 4
        for (int c = 0; c < 64; ++c) {
            float2 wv = *(const float2*)&sW11[c * 64 + 2 * lane];
            ull w0 = pack2(wv.x, wv.x);
            ull w1 = pack2(wv.y, wv.y);
            const float* hr = myH + c * HS;
#pragma unroll
            for (int kk = 0; kk < 4; ++kk) {
                ulonglong2 hv = *(const ulonglong2*)(hr + 4 * kk);  // h[4kk..4kk+3]
                ffma2(acc0[2 * kk],     hv.x, w0);
                ffma2(acc0[2 * kk + 1], hv.y, w0);
                ffma2(acc1[2 * kk],     hv.x, w1);
                ffma2(acc1[2 * kk + 1], hv.y, w1);
            }
        }

        // ---- maxpool over k, bias, relu -> g_P ----
        float m0 = -inff(), m1 = -inff();
#pragma unroll
        for (int kk = 0; kk < 8; ++kk) {
            float a, bh;
            unpack2(acc0[kk], a, bh); m0 = fmaxf(m0, fmaxf(a, bh));
            unpack2(acc1[kk], a, bh); m1 = fmaxf(m1, fmaxf(a, bh));
        }
        float p0 = fmaxf(m0 + bb0, 0.f);
        float p1 = fmaxf(m1 + bb1, 0.f);
        *(float2*)&g_P[(size_t)q * 64 + 2 * lane] = make_float2(p0, p1);
        __syncwarp();
    }
}

// ---------------- final GEMM: out = relu([g_P | feat1] @ W2_0 + b2_0) ----------------
// block: 64 queries x 128 j; thread: 2 queries x 16 j; 24 warps/SM
#define GTHREADS 256
#define AS_S 36                            // duplicated A row: 16c*2 + 4 pad (16B aligned)

__global__ void __launch_bounds__(GTHREADS, 3)
gemm_final(const float* __restrict__ feat1, const float* __restrict__ W2_0,
           const float* __restrict__ b2_0, float* __restrict__ out) {
    __shared__ float As[64 * AS_S];        // 9 KB   A tile [64 q][16 c] duplicated (v,v)
    __shared__ float Bs[16 * 128];         // 8 KB   B tile [16 c][128 j]

    int tid  = threadIdx.x;
    int qg   = tid >> 3;                   // 0..31  -> rows qg, qg+32
    int jblk = tid & 7;                    // 0..7   -> j = jblk*16 .. +16
    int qb   = blockIdx.x * 64;

    ull acc[2][8];
#pragma unroll
    for (int m = 0; m < 2; ++m)
#pragma unroll
        for (int j = 0; j < 8; ++j) acc[m][j] = 0ull;

    // staging roles
    int ar = tid >> 2, ap = tid & 3;       // A: row ar (0..63), c-quad ap
    int br = tid >> 4, bc = (tid & 15) * 8;// B: row br (0..15), 8 cols at bc

    for (int ch = 0; ch < 8; ++ch) {       // 16 c per chunk
        __syncthreads();
        // ---- stage B: W2_0 rows [ch*16, +16) ----
        {
            const float* src = W2_0 + (ch * 16 + br) * 128 + bc;
            float4 v0 = *(const float4*)(src);
            float4 v1 = *(const float4*)(src + 4);
            *(float4*)&Bs[br * 128 + bc]     = v0;
            *(float4*)&Bs[br * 128 + bc + 4] = v1;
        }
        // ---- stage A duplicated: [g_P | feat1] cols [ch*16,+16) for 64 queries ----
        {
            const float* src = (ch < 4)
                ? (g_P   + (size_t)(qb + ar) * 64 + ch * 16)
                : (feat1 + (size_t)(qb + ar) * 64 + (ch - 4) * 16);
            float4 v = *(const float4*)(src + ap * 4);
            *(float4*)&As[ar * AS_S + 8 * ap]     = make_float4(v.x, v.x, v.y, v.y);
            *(float4*)&As[ar * AS_S + 8 * ap + 4] = make_float4(v.z, v.z, v.w, v.w);
        }
        __syncthreads();

#pragma unroll
        for (int cc = 0; cc < 16; ++cc) {
            ull ad0 = *(const ull*)&As[qg * AS_S + 2 * cc];          // (a,a)
            ull ad1 = *(const ull*)&As[(qg + 32) * AS_S + 2 * cc];
            const float* brow = Bs + cc * 128 + jblk * 16;
            ulonglong2 w01 = *(const ulonglong2*)(brow);
            ulonglong2 w23 = *(const ulonglong2*)(brow + 4);
            ulonglong2 w45 = *(const ulonglong2*)(brow + 8);
            ulonglong2 w67 = *(const ulonglong2*)(brow + 12);
            ffma2(acc[0][0], ad0, w01.x);  ffma2(acc[1][0], ad1, w01.x);
            ffma2(acc[0][1], ad0, w01.y);  ffma2(acc[1][1], ad1, w01.y);
            ffma2(acc[0][2], ad0, w23.x);  ffma2(acc[1][2], ad1, w23.x);
            ffma2(acc[0][3], ad0, w23.y);  ffma2(acc[1][3], ad1, w23.y);
            ffma2(acc[0][4], ad0, w45.x);  ffma2(acc[1][4], ad1, w45.x);
            ffma2(acc[0][5], ad0, w45.y);  ffma2(acc[1][5], ad1, w45.y);
            ffma2(acc[0][6], ad0, w67.x);  ffma2(acc[1][6], ad1, w67.x);
            ffma2(acc[0][7], ad0, w67.y);  ffma2(acc[1][7], ad1, w67.y);
        }
    }

    // ---- bias + relu + store ----
    float bias[16];
#pragma unroll
    for (int j = 0; j < 4; ++j)
        *(float4*)&bias[4 * j] = *(const float4*)&b2_0[jblk * 16 + 4 * j];

#pragma unroll
    for (int m = 0; m < 2; ++m) {
        int qq = qb + qg + 32 * m;
        float r[16];
#pragma unroll
        for (int j = 0; j < 8; ++j) {
            float a, bvl;
            unpack2(acc[m][j], a, bvl);
            r[2 * j]     = fmaxf(a   + bias[2 * j],     0.f);
            r[2 * j + 1] = fmaxf(bvl + bias[2 * j + 1], 0.f);
        }
#pragma unroll
        for (int j = 0; j < 4; ++j)
            *(float4*)&out[(size_t)qq * OUTC + jblk * 16 + 4 * j] =
                make_float4(r[4 * j], r[4 * j + 1], r[4 * j + 2], r[4 * j + 3]);
    }
}

// ---------------- launch ----------------
extern "C" void kernel_launch(void* const* d_in, const int* in_sizes, int n_in,
                              void* d_out, int out_size) {
    const float* xyz1  = (const float*)d_in[0];
    const float* feat1 = (const float*)d_in[1];
    const float* xyz2  = (const float*)d_in[2];
    const float* feat2 = (const float*)d_in[3];
    const float* W1_0  = (const float*)d_in[4];
    const float* b1_0  = (const float*)d_in[5];
    const float* W1_1  = (const float*)d_in[6];
    const float* b1_1  = (const float*)d_in[7];
    const float* W2_0  = (const float*)d_in[8];
    const float* b2_0  = (const float*)d_in[9];
    float* out = (float*)d_out;

    cudaFuncSetAttribute(mlp_core, cudaFuncAttributeMaxDynamicSharedMemorySize,
                         CSMEM_B);

    g2_kernel<<<(Bn * N2) / 8, 256>>>(feat2, W1_0, b1_0);
    knn_kernel<<<dim3(N1 / 128, Bn), 128>>>(xyz1, xyz2);
    mlp_core<<<444, CTHREADS, CSMEM_B>>>(xyz1, xyz2, W1_0, W1_1, b1_1);
    gemm_final<<<NQ / 64, GTHREADS>>>(feat1, W2_0, b2_0, out);
}

// round 14
// speedup vs baseline: 1.3135x; 1.3126x over previous
#include <cuda_runtime.h>
#include <cstdint>

typedef unsigned long long ull;

#define Bn   8
#define N1   8192
#define N2   2048
#define KNN  16
#define HID  64
#define OUTC 128
#define NQ   (Bn * N1)

// ---------------- scratch (static device globals; no allocation) ----------------
__device__ int   g_idx[NQ * KNN];          // 4 MB
__device__ float g_G2 [Bn * N2 * HID];     // 4 MB   G2 = feat2 @ W1_0[:64] + b1_0
__device__ float g_P  [NQ * HID];          // 16 MB  pooled layer-2 output

// ---------------- packed f32x2 helpers ----------------
__device__ __forceinline__ void ffma2(ull &d, ull a, ull b) {
    asm("fma.rn.f32x2 %0, %1, %2, %0;" : "+l"(d) : "l"(a), "l"(b));
}
__device__ __forceinline__ ull pack2(float x, float y) {
    ull r; asm("mov.b64 %0, {%1, %2};" : "=l"(r) : "f"(x), "f"(y)); return r;
}
__device__ __forceinline__ void unpack2(ull v, float &x, float &y) {
    asm("mov.b64 {%0, %1}, %2;" : "=f"(x), "=f"(y) : "l"(v));
}
__device__ __forceinline__ float inff() { return __int_as_float(0x7f800000); }

// ---------------- P1: G2 = feat2 @ W1_0[0:64,:] + b1_0 (2 points/thread) ----------------
__global__ void __launch_bounds__(256) g2_kernel(const float* __restrict__ feat2,
                                                 const float* __restrict__ W1_0,
                                                 const float* __restrict__ b1_0) {
    __shared__ float sf[8][64];
    int sub = threadIdx.x >> 6;
    int ch  = threadIdx.x & 63;
    int ptb = blockIdx.x * 8;
    sf[sub][ch]     = feat2[(ptb + sub) * 64 + ch];
    sf[sub + 4][ch] = feat2[(ptb + sub + 4) * 64 + ch];
    __syncthreads();
    const float* r0 = sf[sub];
    const float* r1 = sf[sub + 4];
    float acc0 = b1_0[ch], acc1 = acc0;
#pragma unroll 16
    for (int c = 0; c < 64; ++c) {
        float wv = W1_0[c * 64 + ch];
        acc0 = fmaf(r0[c], wv, acc0);
        acc1 = fmaf(r1[c], wv, acc1);
    }
    g_G2[(ptb + sub) * 64 + ch]     = acc0;
    g_G2[(ptb + sub + 4) * 64 + ch] = acc1;
}

// ---------------- kNN: one query per thread, two-phase select ----------------
__device__ __forceinline__ float distf(float4 p, float x, float y, float z) {
    float t = p.x * x;
    t = fmaf(p.y, y, t);
    t = fmaf(p.z, z, t);
    return fmaf(-2.0f, t, p.w);
}

__global__ void __launch_bounds__(128) knn_kernel(const float* __restrict__ xyz1,
                                                  const float* __restrict__ xyz2) {
    __shared__ float4 s2[N2];                 // 32 KB: (x,y,z,|p|^2)
    int b = blockIdx.y;
    const float* x2 = xyz2 + (size_t)b * N2 * 3;
    for (int i = threadIdx.x; i < N2; i += 128) {
        float px = x2[i * 3 + 0], py = x2[i * 3 + 1], pz = x2[i * 3 + 2];
        s2[i] = make_float4(px, py, pz, fmaf(px, px, fmaf(py, py, pz * pz)));
    }
    __syncthreads();

    int n = blockIdx.x * 128 + threadIdx.x;   // query within batch
    int q = b * N1 + n;
    float x1x = xyz1[q * 3 + 0], x1y = xyz1[q * 3 + 1], x1z = xyz1[q * 3 + 2];

    // phase 1: exact 16th-smallest (shifted) distance via branch-free sorted chain
    float best[KNN];
#pragma unroll
    for (int i = 0; i < KNN; ++i) best[i] = inff();

    for (int c = 0; c < N2; ++c) {
        float4 p = s2[c];
        float d = distf(p, x1x, x1y, x1z);
        bool act = d < best[KNN - 1];
        if (__ballot_sync(0xffffffffu, act)) {
            float v = act ? d : inff();       // INF insert = no-op, keeps warp uniform
#pragma unroll
            for (int i = 0; i < KNN; ++i) {
                float t = fminf(v, best[i]);
                v = fmaxf(v, best[i]);
                best[i] = t;
            }
        }
    }
    float tau = best[KNN - 1];

    // phase 2: collect indices with d <= tau (identical arithmetic), cap at 16
    int cnt = 0, lastc = 0;
    int* myout = g_idx + (size_t)q * KNN;
    for (int c = 0; c < N2; ++c) {
        float4 p = s2[c];
        float d = distf(p, x1x, x1y, x1z);
        if (d <= tau && cnt < KNN) {
            myout[cnt++] = c;
            lastc = c;
        }
    }
    for (; cnt < KNN; ++cnt) myout[cnt] = lastc;   // safety fill (ties/ulp)
}

// ---------------- mlp_core: layer1 + layer2 + maxpool -> g_P ----------------
#define CWARPS   8
#define CTHREADS 256
#define HS       20                        // 16 k-slots + 4 pad (16B-aligned rows)
#define SW11_F   4096                      // 64*64 W1_1 (not duplicated)
#define SHW_F    (64 * HS)                 // per-warp H1 buffer (1280 floats)
#define CSMEM_F  (SW11_F + CWARPS * SHW_F + CWARPS * 16)
#define CSMEM_B  (CSMEM_F * 4)             // ~57 KB -> 3 blocks/SM

__global__ void __launch_bounds__(CTHREADS, 3)
mlp_core(const float* __restrict__ xyz1, const float* __restrict__ xyz2,
         const float* __restrict__ W1_0, const float* __restrict__ W1_1,
         const float* __restrict__ b1_1) {
    extern __shared__ float sm[];
    float* sW11 = sm;
    float* sH   = sm + SW11_F;
    int*   sIdx = (int*)(sm + SW11_F + CWARPS * SHW_F);

    int tid = threadIdx.x, w = tid >> 5, lane = tid & 31;

    for (int i = tid; i < SW11_F; i += CTHREADS) sW11[i] = W1_1[i];

    // per-lane constants: xyz rows of W1_0 for channels (lane, lane+32); layer-2 bias
    float wxa = W1_0[64 * 64 + lane],      wxb = W1_0[64 * 64 + lane + 32];
    float wya = W1_0[65 * 64 + lane],      wyb = W1_0[65 * 64 + lane + 32];
    float wza = W1_0[66 * 64 + lane],      wzb = W1_0[66 * 64 + lane + 32];
    float bb0 = b1_1[2 * lane], bb1 = b1_1[2 * lane + 1];
    __syncthreads();

    float* myH   = sH + w * SHW_F;
    int*   myIdx = sIdx + w * 16;
    const int nwarps = gridDim.x * CWARPS;

    for (int q = blockIdx.x * CWARPS + w; q < NQ; q += nwarps) {
        int b = q >> 13;
        if (lane < 16) myIdx[lane] = g_idx[(size_t)q * KNN + lane];
        float x1x = xyz1[q * 3 + 0], x1y = xyz1[q * 3 + 1], x1z = xyz1[q * 3 + 2];
        __syncwarp();

        // ---- layer 1: lane owns channels (lane, lane+32) ----
#pragma unroll
        for (int k = 0; k < KNN; ++k) {
            int ik = myIdx[k];
            const float* gr = g_G2 + ((size_t)(b << 11) + ik) * 64;
            float g0 = gr[lane], g1 = gr[lane + 32];
            const float* p2 = xyz2 + ((size_t)(b << 11) + ik) * 3;
            float dx = p2[0] - x1x, dy = p2[1] - x1y, dz = p2[2] - x1z;
            float h0 = fmaf(dz, wza, fmaf(dy, wya, fmaf(dx, wxa, g0)));
            float h1 = fmaf(dz, wzb, fmaf(dy, wyb, fmaf(dx, wxb, g1)));
            myH[lane * HS + k]        = fmaxf(h0, 0.f);
            myH[(lane + 32) * HS + k] = fmaxf(h1, 0.f);
        }
        __syncwarp();

        // ---- layer 2: FFMA2, 16B broadcast H reads, pack weights on the fly ----
        ull acc0[8], acc1[8];
#pragma unroll
        for (int kk = 0; kk < 8; ++kk) { acc0[kk] = 0ull; acc1[kk] = 0ull; }
#pragma unroll 4
        for (int c = 0; c < 64; ++c) {
            float2 wv = *(const float2*)&sW11[c * 64 + 2 * lane];
            ull w0 = pack2(wv.x, wv.x);
            ull w1 = pack2(wv.y, wv.y);
            const float* hr = myH + c * HS;
#pragma unroll
            for (int kk = 0; kk < 4; ++kk) {
                ulonglong2 hv = *(const ulonglong2*)(hr + 4 * kk);  // h[4kk..4kk+3]
                ffma2(acc0[2 * kk],     hv.x, w0);
                ffma2(acc0[2 * kk + 1], hv.y, w0);
                ffma2(acc1[2 * kk],     hv.x, w1);
                ffma2(acc1[2 * kk + 1], hv.y, w1);
            }
        }

        // ---- maxpool over k, bias, relu -> g_P ----
        float m0 = -inff(), m1 = -inff();
#pragma unroll
        for (int kk = 0; kk < 8; ++kk) {
            float a, bh;
            unpack2(acc0[kk], a, bh); m0 = fmaxf(m0, fmaxf(a, bh));
            unpack2(acc1[kk], a, bh); m1 = fmaxf(m1, fmaxf(a, bh));
        }
        float p0 = fmaxf(m0 + bb0, 0.f);
        float p1 = fmaxf(m1 + bb1, 0.f);
        *(float2*)&g_P[(size_t)q * 64 + 2 * lane] = make_float2(p0, p1);
        __syncwarp();
    }
}

// ---------------- final GEMM: out = relu([g_P | feat1] @ W2_0 + b2_0) ----------------
// block: 64 q x 128 j; thread: 2 q x 16 j, columns interleaved {32g + 4*jblk + e}
// -> each per-cc weight LDS.128 covers a contiguous 128B across the 8 jblk groups
//    (conflict-free, broadcast-deduped: 1 wavefront instead of 4)
#define GTHREADS 256
#define AS_S 36                            // duplicated A row: 16c*2 + 4 pad (16B aligned)

__global__ void __launch_bounds__(GTHREADS, 3)
gemm_final(const float* __restrict__ feat1, const float* __restrict__ W2_0,
           const float* __restrict__ b2_0, float* __restrict__ out) {
    __shared__ float As[64 * AS_S];        // 9 KB   A tile [64 q][16 c] duplicated (v,v)
    __shared__ float Bs[16 * 128];         // 8 KB   B tile [16 c][128 j]

    int tid  = threadIdx.x;
    int qg   = tid >> 3;                   // 0..31  -> rows qg, qg+32
    int jblk = tid & 7;                    // 0..7   -> cols 32*g + 4*jblk + e
    int qb   = blockIdx.x * 64;

    ull acc[2][4][2];                      // [m][g][pair-of-2-cols]
#pragma unroll
    for (int m = 0; m < 2; ++m)
#pragma unroll
        for (int g = 0; g < 4; ++g) { acc[m][g][0] = 0ull; acc[m][g][1] = 0ull; }

    // staging roles
    int ar = tid >> 2, ap = tid & 3;       // A: row ar (0..63), c-quad ap
    int br = tid >> 4, bc = (tid & 15) * 8;// B: row br (0..15), 8 cols at bc

    for (int ch = 0; ch < 8; ++ch) {       // 16 c per chunk
        __syncthreads();
        // ---- stage B: W2_0 rows [ch*16, +16) (natural [c][j] layout) ----
        {
            const float* src = W2_0 + (ch * 16 + br) * 128 + bc;
            float4 v0 = *(const float4*)(src);
            float4 v1 = *(const float4*)(src + 4);
            *(float4*)&Bs[br * 128 + bc]     = v0;
            *(float4*)&Bs[br * 128 + bc + 4] = v1;
        }
        // ---- stage A duplicated: [g_P | feat1] cols [ch*16,+16) for 64 queries ----
        {
            const float* src = (ch < 4)
                ? (g_P   + (size_t)(qb + ar) * 64 + ch * 16)
                : (feat1 + (size_t)(qb + ar) * 64 + (ch - 4) * 16);
            float4 v = *(const float4*)(src + ap * 4);
            *(float4*)&As[ar * AS_S + 8 * ap]     = make_float4(v.x, v.x, v.y, v.y);
            *(float4*)&As[ar * AS_S + 8 * ap + 4] = make_float4(v.z, v.z, v.w, v.w);
        }
        __syncthreads();

#pragma unroll
        for (int cc = 0; cc < 16; ++cc) {
            ull ad0 = *(const ull*)&As[qg * AS_S + 2 * cc];          // (a,a)
            ull ad1 = *(const ull*)&As[(qg + 32) * AS_S + 2 * cc];
            const float* brow = Bs + cc * 128 + 4 * jblk;
#pragma unroll
            for (int g = 0; g < 4; ++g) {
                ulonglong2 wv = *(const ulonglong2*)(brow + 32 * g); // cols 32g+4jblk..+3
                ffma2(acc[0][g][0], ad0, wv.x);
                ffma2(acc[0][g][1], ad0, wv.y);
                ffma2(acc[1][g][0], ad1, wv.x);
                ffma2(acc[1][g][1], ad1, wv.y);
            }
        }
    }

    // ---- bias + relu + store (interleaved columns) ----
#pragma unroll
    for (int g = 0; g < 4; ++g) {
        float4 bias = *(const float4*)&b2_0[32 * g + 4 * jblk];
#pragma unroll
        for (int m = 0; m < 2; ++m) {
            int qq = qb + qg + 32 * m;
            float r0, r1, r2, r3;
            unpack2(acc[m][g][0], r0, r1);
            unpack2(acc[m][g][1], r2, r3);
            float4 res = make_float4(fmaxf(r0 + bias.x, 0.f),
                                     fmaxf(r1 + bias.y, 0.f),
                                     fmaxf(r2 + bias.z, 0.f),
                                     fmaxf(r3 + bias.w, 0.f));
            *(float4*)&out[(size_t)qq * OUTC + 32 * g + 4 * jblk] = res;
        }
    }
}

// ---------------- launch ----------------
extern "C" void kernel_launch(void* const* d_in, const int* in_sizes, int n_in,
                              void* d_out, int out_size) {
    const float* xyz1  = (const float*)d_in[0];
    const float* feat1 = (const float*)d_in[1];
    const float* xyz2  = (const float*)d_in[2];
    const float* feat2 = (const float*)d_in[3];
    const float* W1_0  = (const float*)d_in[4];
    const float* b1_0  = (const float*)d_in[5];
    const float* W1_1  = (const float*)d_in[6];
    const float* b1_1  = (const float*)d_in[7];
    const float* W2_0  = (const float*)d_in[8];
    const float* b2_0  = (const float*)d_in[9];
    float* out = (float*)d_out;

    cudaFuncSetAttribute(mlp_core, cudaFuncAttributeMaxDynamicSharedMemorySize,
                         CSMEM_B);

    g2_kernel<<<(Bn * N2) / 8, 256>>>(feat2, W1_0, b1_0);
    knn_kernel<<<dim3(N1 / 128, Bn), 128>>>(xyz1, xyz2);
    mlp_core<<<444, CTHREADS, CSMEM_B>>>(xyz1, xyz2, W1_0, W1_1, b1_1);
    gemm_final<<<NQ / 64, GTHREADS>>>(feat1, W2_0, b2_0, out);
}